// round 8
// baseline (speedup 1.0000x reference)
#include <cuda_runtime.h>
#include <cuda_bf16.h>
#include <cstdint>

// ---------------------------------------------------------------------------
// EGNN layer, fused.
//   zero_kernel:   clear accumulators + dtype-detect flag
//   detect_kernel: sniff whether edge_index is int32 or int64
//   edge_kernel:   4 edges/warp: gather -> edge MLP (GEMV from SMEM weights,
//                  weights amortized across 4 edges) -> s-gate -> gamma ->
//                  vectorized atomic scatter-add
//   node_kernel:   degree-normalize -> node MLP -> x_out, pos_out
// All fp32.
// ---------------------------------------------------------------------------

#define NMAX 50048

#define NW_E 8            // warps per block, edge kernel (2 per SMSP, even)
#define TPB_E (NW_E * 32)
#define ED 4              // edges per warp

#define NW_N 12           // warps per block, node kernel
#define TPB_N (NW_N * 32)

__device__ __align__(16) float g_msum[(size_t)NMAX * 128];
__device__ __align__(16) float g_coord[(size_t)NMAX * 3];
__device__ __align__(16) float g_deg[NMAX];
__device__ int g_or;      // 0 => indices are int64, nonzero => int32

__device__ __forceinline__ float silu_f(float v) {
    return __fdividef(v, 1.0f + __expf(-v));
}

__device__ __forceinline__ void red_add_v4(float* addr, float4 v) {
    asm volatile("red.global.add.v4.f32 [%0], {%1,%2,%3,%4};"
                 :: "l"(addr), "f"(v.x), "f"(v.y), "f"(v.z), "f"(v.w)
                 : "memory");
}

#define FMA4(h, v, wv)                    \
    h.x = fmaf((v), (wv).x, h.x);         \
    h.y = fmaf((v), (wv).y, h.y);         \
    h.z = fmaf((v), (wv).z, h.z);         \
    h.w = fmaf((v), (wv).w, h.w)

#define SILU4(h)                          \
    h.x = silu_f(h.x); h.y = silu_f(h.y); \
    h.z = silu_f(h.z); h.w = silu_f(h.w)

// ------------------------------- zero ---------------------------------------
__global__ void zero_kernel(int n) {
    int i = blockIdx.x * blockDim.x + threadIdx.x;
    int stride = gridDim.x * blockDim.x;
    if (i == 0) g_or = 0;
    int total = n * 128;
    for (int j = i; j < total; j += stride) g_msum[j] = 0.0f;
    for (int j = i; j < n * 3; j += stride) g_coord[j] = 0.0f;
    for (int j = i; j < n;     j += stride) g_deg[j]   = 0.0f;
}

// ------------------------------- detect --------------------------------------
// If edge_index is int64 with values in [0, 2^31), every odd 32-bit word is 0.
// If it is int32 (random indices), the OR of 8192 samples is ~surely nonzero.
__global__ void detect_kernel(const unsigned int* w, int E) {
    unsigned acc = 0;
    int lim = E < 8192 ? E : 8192;
    for (int i = blockIdx.x * blockDim.x + threadIdx.x; i < lim;
         i += gridDim.x * blockDim.x)
        acc |= w[2 * i + 1];
    if (acc) atomicOr(&g_or, 1);
}

// ------------------------------- edge ---------------------------------------
// SMEM (floats): sW1[258*128] sW2[128*128] sWc[128] sb1[128] sb2[128]
//                sE[NW_E * ED * 256]          -> 231,936 bytes total
__global__ __launch_bounds__(TPB_E, 1)
void edge_kernel(const float* __restrict__ x, const float* __restrict__ pos,
                 const int* __restrict__ ei32, const long long* __restrict__ ei64,
                 const float* __restrict__ eattr, const float* __restrict__ s,
                 const float* __restrict__ We1, const float* __restrict__ be1,
                 const float* __restrict__ We2, const float* __restrict__ be2,
                 const float* __restrict__ Wc,  const float* __restrict__ bc,
                 int E, int Nn)
{
    extern __shared__ float sm[];
    float* sW1 = sm;                    // 33024
    float* sW2 = sW1 + 258 * 128;       // 16384
    float* sWc = sW2 + 128 * 128;       // 128
    float* sb1 = sWc + 128;             // 128
    float* sb2 = sb1 + 128;             // 128
    float* sE  = sb2 + 128;             // NW_E * ED * 256

    const int tid = threadIdx.x;
    for (int i = tid; i < (258 * 128) / 4; i += TPB_E)
        ((float4*)sW1)[i] = ((const float4*)We1)[i];
    for (int i = tid; i < (128 * 128) / 4; i += TPB_E)
        ((float4*)sW2)[i] = ((const float4*)We2)[i];
    for (int i = tid; i < 128; i += TPB_E) {
        sWc[i] = Wc[i]; sb1[i] = be1[i]; sb2[i] = be2[i];
    }
    __syncthreads();

    const bool idx64 = (g_or == 0);
    const float bcv  = bc[0];
    const int lane   = tid & 31;
    const int w      = tid >> 5;
    float* eb = sE + w * (ED * 256);

    const int gw = blockIdx.x * NW_E + w;
    const int nw = gridDim.x * NW_E;

    for (long long b0 = (long long)gw * ED; b0 < E; b0 += (long long)nw * ED) {
        int   srcv[ED], dstv[ED];
        bool  ok[ED];
        float dx[ED], dy[ED], dz[ED], r2v[ED], eav[ED], sgv[ED];

        __syncwarp();   // previous iteration fully done reading eb

        #pragma unroll
        for (int g = 0; g < ED; g++) {
            long long e = b0 + g;
            ok[g] = (e < (long long)E);
            int ss = 0, dd = 0;
            if (ok[g]) {
                if (idx64) { ss = (int)ei64[e]; dd = (int)ei64[E + e]; }
                else       { ss = ei32[e];      dd = ei32[E + e]; }
                if ((unsigned)ss >= (unsigned)Nn || (unsigned)dd >= (unsigned)Nn) {
                    ok[g] = false; ss = 0; dd = 0;
                }
            }
            srcv[g] = ss; dstv[g] = dd;

            dx[g] = pos[dd * 3 + 0] - pos[ss * 3 + 0];
            dy[g] = pos[dd * 3 + 1] - pos[ss * 3 + 1];
            dz[g] = pos[dd * 3 + 2] - pos[ss * 3 + 2];
            r2v[g] = dx[g]*dx[g] + dy[g]*dy[g] + dz[g]*dz[g];
            eav[g] = ok[g] ? eattr[e] : 0.0f;
            sgv[g] = s[ss];

            float4 xd = *(const float4*)(x + (size_t)dd * 128 + lane * 4);
            float4 xs = *(const float4*)(x + (size_t)ss * 128 + lane * 4);
            *(float4*)(eb + g * 256 + lane * 4)       = xd;
            *(float4*)(eb + g * 256 + 128 + lane * 4) = xs;
        }
        __syncwarp();

        // ---- layer 1: 258 -> 128, SiLU (k=256,257 handled from registers) ----
        float4 bb = *(const float4*)(sb1 + lane * 4);
        float4 h0 = bb, h1 = bb, h2 = bb, h3 = bb;
        #pragma unroll 4
        for (int k = 0; k < 256; k++) {
            const float4 wv = *(const float4*)(sW1 + k * 128 + lane * 4);
            const float v0 = eb[0 * 256 + k];
            const float v1 = eb[1 * 256 + k];
            const float v2 = eb[2 * 256 + k];
            const float v3 = eb[3 * 256 + k];
            FMA4(h0, v0, wv); FMA4(h1, v1, wv);
            FMA4(h2, v2, wv); FMA4(h3, v3, wv);
        }
        {
            const float4 wa = *(const float4*)(sW1 + 256 * 128 + lane * 4);
            const float4 wb = *(const float4*)(sW1 + 257 * 128 + lane * 4);
            FMA4(h0, r2v[0], wa); FMA4(h0, eav[0], wb);
            FMA4(h1, r2v[1], wa); FMA4(h1, eav[1], wb);
            FMA4(h2, r2v[2], wa); FMA4(h2, eav[2], wb);
            FMA4(h3, r2v[3], wa); FMA4(h3, eav[3], wb);
        }
        SILU4(h0); SILU4(h1); SILU4(h2); SILU4(h3);

        __syncwarp();                 // all lanes done reading eb (layer-1 input)
        *(float4*)(eb + 0 * 256 + lane * 4) = h0;
        *(float4*)(eb + 1 * 256 + lane * 4) = h1;
        *(float4*)(eb + 2 * 256 + lane * 4) = h2;
        *(float4*)(eb + 3 * 256 + lane * 4) = h3;
        __syncwarp();

        // ---- layer 2: 128 -> 128, SiLU ----
        const float4 b2 = *(const float4*)(sb2 + lane * 4);
        float4 m0 = b2, m1 = b2, m2 = b2, m3 = b2;
        #pragma unroll 4
        for (int k = 0; k < 128; k++) {
            const float4 wv = *(const float4*)(sW2 + k * 128 + lane * 4);
            const float v0 = eb[0 * 256 + k];
            const float v1 = eb[1 * 256 + k];
            const float v2 = eb[2 * 256 + k];
            const float v3 = eb[3 * 256 + k];
            FMA4(m0, v0, wv); FMA4(m1, v1, wv);
            FMA4(m2, v2, wv); FMA4(m3, v3, wv);
        }
        SILU4(m0); SILU4(m1); SILU4(m2); SILU4(m3);

        // s-gate
        m0.x *= sgv[0]; m0.y *= sgv[0]; m0.z *= sgv[0]; m0.w *= sgv[0];
        m1.x *= sgv[1]; m1.y *= sgv[1]; m1.z *= sgv[1]; m1.w *= sgv[1];
        m2.x *= sgv[2]; m2.y *= sgv[2]; m2.z *= sgv[2]; m2.w *= sgv[2];
        m3.x *= sgv[3]; m3.y *= sgv[3]; m3.z *= sgv[3]; m3.w *= sgv[3];

        // gamma_g = m_g . Wc + bc  (warp reductions)
        const float4 wc = *(const float4*)(sWc + lane * 4);
        float p0 = m0.x*wc.x + m0.y*wc.y + m0.z*wc.z + m0.w*wc.w;
        float p1 = m1.x*wc.x + m1.y*wc.y + m1.z*wc.z + m1.w*wc.w;
        float p2 = m2.x*wc.x + m2.y*wc.y + m2.z*wc.z + m2.w*wc.w;
        float p3 = m3.x*wc.x + m3.y*wc.y + m3.z*wc.z + m3.w*wc.w;
        #pragma unroll
        for (int o = 16; o; o >>= 1) {
            p0 += __shfl_xor_sync(0xffffffffu, p0, o);
            p1 += __shfl_xor_sync(0xffffffffu, p1, o);
            p2 += __shfl_xor_sync(0xffffffffu, p2, o);
            p3 += __shfl_xor_sync(0xffffffffu, p3, o);
        }
        const float gam[ED] = {p0 + bcv, p1 + bcv, p2 + bcv, p3 + bcv};

        // scatter-add
        if (ok[0]) red_add_v4(g_msum + (size_t)dstv[0] * 128 + lane * 4, m0);
        if (ok[1]) red_add_v4(g_msum + (size_t)dstv[1] * 128 + lane * 4, m1);
        if (ok[2]) red_add_v4(g_msum + (size_t)dstv[2] * 128 + lane * 4, m2);
        if (ok[3]) red_add_v4(g_msum + (size_t)dstv[3] * 128 + lane * 4, m3);
        if (lane < ED && ok[lane]) {
            const int g = lane, dd = dstv[lane];
            atomicAdd(g_coord + dd * 3 + 0, gam[g] * dx[g]);
            atomicAdd(g_coord + dd * 3 + 1, gam[g] * dy[g]);
            atomicAdd(g_coord + dd * 3 + 2, gam[g] * dz[g]);
            atomicAdd(g_deg + dd, 1.0f);
        }
    }
}

// ------------------------------- node ---------------------------------------
// SMEM: sWn1[256*128] sWn2[128*128] sbn1[128] sbn2[128] sEin[NW_N*256] sH[NW_N*128]
__global__ __launch_bounds__(TPB_N, 1)
void node_kernel(const float* __restrict__ x, const float* __restrict__ pos,
                 const float* __restrict__ Wn1, const float* __restrict__ bn1,
                 const float* __restrict__ Wn2, const float* __restrict__ bn2,
                 float* __restrict__ xout, float* __restrict__ posout,
                 int N)
{
    extern __shared__ float sm[];
    float* sWn1 = sm;
    float* sWn2 = sWn1 + 256 * 128;
    float* sbn1 = sWn2 + 128 * 128;
    float* sbn2 = sbn1 + 128;
    float* sEin = sbn2 + 128;
    float* sH   = sEin + NW_N * 256;

    const int tid = threadIdx.x;
    for (int i = tid; i < (256 * 128) / 4; i += TPB_N)
        ((float4*)sWn1)[i] = ((const float4*)Wn1)[i];
    for (int i = tid; i < (128 * 128) / 4; i += TPB_N)
        ((float4*)sWn2)[i] = ((const float4*)Wn2)[i];
    for (int i = tid; i < 128; i += TPB_N) { sbn1[i] = bn1[i]; sbn2[i] = bn2[i]; }
    __syncthreads();

    const int lane = tid & 31;
    const int w    = tid >> 5;
    float* ein = sEin + w * 256;
    float* hb  = sH   + w * 128;

    const int gw = blockIdx.x * NW_N + w;
    const int nw = gridDim.x * NW_N;

    for (int n = gw; n < N; n += nw) {
        float dg = fmaxf(g_deg[n], 1.0f);
        const float inv = 1.0f / dg;

        float4 xr = *(const float4*)(x + (size_t)n * 128 + lane * 4);
        float4 ms = *(const float4*)(g_msum + (size_t)n * 128 + lane * 4);
        ms.x *= inv; ms.y *= inv; ms.z *= inv; ms.w *= inv;
        __syncwarp();
        *(float4*)(ein + lane * 4)       = xr;
        *(float4*)(ein + 128 + lane * 4) = ms;
        __syncwarp();

        float4 h = *(const float4*)(sbn1 + lane * 4);
        #pragma unroll 4
        for (int k = 0; k < 256; k++) {
            const float v = ein[k];
            const float4 wv = *(const float4*)(sWn1 + k * 128 + lane * 4);
            FMA4(h, v, wv);
        }
        SILU4(h);

        __syncwarp();
        *(float4*)(hb + lane * 4) = h;
        __syncwarp();

        float4 o = *(const float4*)(sbn2 + lane * 4);
        #pragma unroll 4
        for (int k = 0; k < 128; k++) {
            const float v = hb[k];
            const float4 wv = *(const float4*)(sWn2 + k * 128 + lane * 4);
            FMA4(o, v, wv);
        }
        *(float4*)(xout + (size_t)n * 128 + lane * 4) = o;

        if (lane < 3)
            posout[n * 3 + lane] = pos[n * 3 + lane] + g_coord[n * 3 + lane] * inv;
    }
}

// ------------------------------- launch --------------------------------------
extern "C" void kernel_launch(void* const* d_in, const int* in_sizes, int n_in,
                              void* d_out, int out_size) {
    const float* x     = (const float*)d_in[0];
    const float* pos   = (const float*)d_in[1];
    const void*  ei    = d_in[2];
    const float* eattr = (const float*)d_in[3];
    const float* s     = (const float*)d_in[4];
    const float* We1   = (const float*)d_in[5];
    const float* be1   = (const float*)d_in[6];
    const float* We2   = (const float*)d_in[7];
    const float* be2   = (const float*)d_in[8];
    const float* Wn1   = (const float*)d_in[9];
    const float* bn1   = (const float*)d_in[10];
    const float* Wn2   = (const float*)d_in[11];
    const float* bn2   = (const float*)d_in[12];
    const float* Wc    = (const float*)d_in[13];
    const float* bc    = (const float*)d_in[14];

    const int N = in_sizes[0] / 128;
    const int E = in_sizes[2] / 2;

    float* xout   = (float*)d_out;
    float* posout = (float*)d_out + (size_t)N * 128;

    int dev = 0, nsm = 148;
    cudaGetDevice(&dev);
    cudaDeviceGetAttribute(&nsm, cudaDevAttrMultiProcessorCount, dev);

    const size_t smem_edge = (size_t)(258 * 128 + 128 * 128 + 3 * 128 +
                                      NW_E * ED * 256) * sizeof(float);   // 231,936
    const size_t smem_node = (size_t)(256 * 128 + 128 * 128 + 2 * 128 +
                                      NW_N * 256 + NW_N * 128) * sizeof(float); // 216,064

    cudaFuncSetAttribute(edge_kernel, cudaFuncAttributeMaxDynamicSharedMemorySize,
                         (int)smem_edge);
    cudaFuncSetAttribute(node_kernel, cudaFuncAttributeMaxDynamicSharedMemorySize,
                         (int)smem_node);

    zero_kernel<<<256, 256>>>(N);
    detect_kernel<<<16, 256>>>((const unsigned int*)ei, E);
    edge_kernel<<<nsm, TPB_E, smem_edge>>>(x, pos,
                                           (const int*)ei, (const long long*)ei,
                                           eattr, s,
                                           We1, be1, We2, be2, Wc, bc, E, N);
    node_kernel<<<nsm, TPB_N, smem_node>>>(x, pos, Wn1, bn1, Wn2, bn2,
                                           xout, posout, N);
}

// round 11
// speedup vs baseline: 1.2581x; 1.2581x over previous
#include <cuda_runtime.h>
#include <cuda_bf16.h>
#include <cstdint>

// ---------------------------------------------------------------------------
// EGNN layer, fused, f32x2 (FFMA2) GEMV path.
//   zero_kernel:   clear accumulators + dtype-detect flag
//   detect_kernel: sniff whether edge_index is int32 or int64
//   edge_kernel:   8 edges/warp, packed-f32x2 GEMV from swizzled SMEM weights
//   node_kernel:   4 nodes/warp, same scheme
// Accumulation is k-pairwise in f32x2 lanes; weights stored k-pair interleaved
// with a 16B XOR swizzle for conflict-free LDS.128.
// ---------------------------------------------------------------------------

#define NMAX 50048

#define NW_E 4
#define TPB_E (NW_E * 32)   // 128
#define ED 8                // edges per warp

#define NW_N 8
#define TPB_N (NW_N * 32)   // 256
#define ND 4                // nodes per warp

__device__ __align__(16) float g_msum[(size_t)NMAX * 128];
__device__ __align__(16) float g_coord[(size_t)NMAX * 3];
__device__ __align__(16) float g_deg[NMAX];
__device__ int g_or;        // 0 => indices are int64, nonzero => int32

__device__ __forceinline__ float silu_f(float v) {
    return __fdividef(v, 1.0f + __expf(-v));
}

__device__ __forceinline__ void red_add_v4(float* addr, float4 v) {
    asm volatile("red.global.add.v4.f32 [%0], {%1,%2,%3,%4};"
                 :: "l"(addr), "f"(v.x), "f"(v.y), "f"(v.z), "f"(v.w)
                 : "memory");
}

__device__ __forceinline__ void fma2(unsigned long long& a,
                                     unsigned long long v,
                                     unsigned long long w) {
    asm("fma.rn.f32x2 %0, %1, %2, %0;" : "+l"(a) : "l"(v), "l"(w));
}
__device__ __forceinline__ float lohi_sum(unsigned long long a) {
    float lo, hi;
    asm("mov.b64 {%0,%1}, %2;" : "=f"(lo), "=f"(hi) : "l"(a));
    return lo + hi;
}
__device__ __forceinline__ unsigned long long packf2(float lo, float hi) {
    unsigned long long r;
    asm("mov.b64 %0, {%1,%2};" : "=l"(r) : "f"(lo), "f"(hi));
    return r;
}

// Swizzled index for k-pair interleaved weight storage.
// Logical W[k][j] (j = 0..127). Row = k/2 (256 floats). Within a row, lane
// L = (j*2+(k&1))/8 owns a 32B group (4 outputs x 2 k). The two 16B chunks of
// each group are swapped when (L>>2)&1 to make warp-wide LDS.128 conflict-free.
__device__ __forceinline__ int wswz(int k, int j) {
    int k2 = k >> 1, p = k & 1;
    int col = j * 2 + p;             // 0..255
    int L = col >> 3;                // owning lane
    int o = col & 7;
    int c = o >> 2;                  // chunk 0/1
    int pos = o & 3;
    return k2 * 256 + (L * 2 + (c ^ ((L >> 2) & 1))) * 4 + pos;
}

// ------------------------------- zero ---------------------------------------
__global__ void zero_kernel(int n) {
    int i = blockIdx.x * blockDim.x + threadIdx.x;
    int stride = gridDim.x * blockDim.x;
    if (i == 0) g_or = 0;
    int total = n * 128;
    for (int j = i; j < total; j += stride) g_msum[j] = 0.0f;
    for (int j = i; j < n * 3; j += stride) g_coord[j] = 0.0f;
    for (int j = i; j < n;     j += stride) g_deg[j]   = 0.0f;
}

// ------------------------------- detect --------------------------------------
__global__ void detect_kernel(const unsigned int* w, int E) {
    unsigned acc = 0;
    int lim = E < 8192 ? E : 8192;
    for (int i = blockIdx.x * blockDim.x + threadIdx.x; i < lim;
         i += gridDim.x * blockDim.x)
        acc |= w[2 * i + 1];
    if (acc) atomicOr(&g_or, 1);
}

// ------------------------------- edge ---------------------------------------
// SMEM floats: sW1[129*256]=33024  sW2[64*256]=16384  sWc/sb1/sb2[384]
//              sE[NW_E*ED*256]=8192   -> 57984 floats = 231,936 B
__global__ __launch_bounds__(TPB_E, 1)
void edge_kernel(const float* __restrict__ x, const float* __restrict__ pos,
                 const int* __restrict__ ei32, const long long* __restrict__ ei64,
                 const float* __restrict__ eattr, const float* __restrict__ s,
                 const float* __restrict__ We1, const float* __restrict__ be1,
                 const float* __restrict__ We2, const float* __restrict__ be2,
                 const float* __restrict__ Wc,  const float* __restrict__ bc,
                 int E, int Nn)
{
    extern __shared__ float sm[];
    float* sW1 = sm;                  // 129 k2-rows x 256
    float* sW2 = sW1 + 129 * 256;     // 64 k2-rows x 256
    float* sWc = sW2 + 64 * 256;
    float* sb1 = sWc + 128;
    float* sb2 = sb1 + 128;
    float* sE  = sb2 + 128;

    const int tid = threadIdx.x;
    for (int idx = tid; idx < 258 * 128; idx += TPB_E) {
        int k = idx >> 7, j = idx & 127;
        sW1[wswz(k, j)] = We1[idx];
    }
    for (int idx = tid; idx < 128 * 128; idx += TPB_E) {
        int k = idx >> 7, j = idx & 127;
        sW2[wswz(k, j)] = We2[idx];
    }
    for (int i = tid; i < 128; i += TPB_E) {
        sWc[i] = Wc[i]; sb1[i] = be1[i]; sb2[i] = be2[i];
    }
    __syncthreads();

    const bool idx64 = (g_or == 0);
    const float bcv  = bc[0];
    const int lane   = tid & 31;
    const int w      = tid >> 5;
    float* eb = sE + w * (ED * 256);

    const int wofs = lane * 8;
    const int s4   = ((lane >> 2) & 1) * 4;
    const float4 sb1v = *(const float4*)(sb1 + lane * 4);
    const float4 sb2v = *(const float4*)(sb2 + lane * 4);
    const float4 wcv  = *(const float4*)(sWc + lane * 4);

    const long long bstride = (long long)gridDim.x * NW_E * ED;
    for (long long b0 = ((long long)blockIdx.x * NW_E + w) * ED;
         b0 < E; b0 += bstride) {

        // ---- lane-distributed per-edge metadata (lane g owns edge b0+g) ----
        long long e = b0 + lane;
        bool have = (lane < ED) && (e < (long long)E);
        int ss = 0, dd = 0;
        if (have) {
            if (idx64) { ss = (int)ei64[e]; dd = (int)ei64[E + e]; }
            else       { ss = ei32[e];      dd = ei32[E + e]; }
            if ((unsigned)ss >= (unsigned)Nn || (unsigned)dd >= (unsigned)Nn) {
                have = false; ss = 0; dd = 0;
            }
        }
        float dx = 0.f, dy = 0.f, dz = 0.f, r2 = 0.f, ea = 0.f, sg = 0.f;
        if (lane < ED) {
            dx = pos[dd * 3 + 0] - pos[ss * 3 + 0];
            dy = pos[dd * 3 + 1] - pos[ss * 3 + 1];
            dz = pos[dd * 3 + 2] - pos[ss * 3 + 2];
            r2 = dx * dx + dy * dy + dz * dz;
            ea = have ? eattr[e] : 0.0f;
            sg = s[ss];
        }
        const int okflag = have ? 1 : 0;

        __syncwarp();
        // ---- gather x[dst], x[src] into eb (all lanes cooperate) ----
        #pragma unroll
        for (int g = 0; g < ED; g++) {
            int dg  = __shfl_sync(0xffffffffu, dd, g);
            int sgi = __shfl_sync(0xffffffffu, ss, g);
            float4 xd = *(const float4*)(x + (size_t)dg  * 128 + lane * 4);
            float4 xs = *(const float4*)(x + (size_t)sgi * 128 + lane * 4);
            *(float4*)(eb + g * 256 + lane * 4)       = xd;
            *(float4*)(eb + g * 256 + 128 + lane * 4) = xs;
        }
        __syncwarp();

        // ---- layer 1: 258 -> 128, f32x2, SiLU ----
        unsigned long long acc[ED][4];
        #pragma unroll
        for (int g = 0; g < ED; g++)
            acc[g][0] = acc[g][1] = acc[g][2] = acc[g][3] = 0ull;

        #pragma unroll 4
        for (int k4 = 0; k4 < 64; k4++) {
            const float* r0 = sW1 + (k4 * 2) * 256 + wofs;
            ulonglong2 a0 = *(const ulonglong2*)(r0 + s4);
            ulonglong2 c0 = *(const ulonglong2*)(r0 + 4 - s4);
            ulonglong2 a1 = *(const ulonglong2*)(r0 + 256 + s4);
            ulonglong2 c1 = *(const ulonglong2*)(r0 + 256 + 4 - s4);
            #pragma unroll
            for (int g = 0; g < ED; g++) {
                ulonglong2 v = *(const ulonglong2*)(eb + g * 256 + k4 * 4);
                fma2(acc[g][0], v.x, a0.x); fma2(acc[g][1], v.x, a0.y);
                fma2(acc[g][2], v.x, c0.x); fma2(acc[g][3], v.x, c0.y);
                fma2(acc[g][0], v.y, a1.x); fma2(acc[g][1], v.y, a1.y);
                fma2(acc[g][2], v.y, c1.x); fma2(acc[g][3], v.y, c1.y);
            }
        }
        {   // tail k-pair (k=256: r2, k=257: edge_attr) = k2 row 128
            const float* rt = sW1 + 128 * 256 + wofs;
            ulonglong2 at = *(const ulonglong2*)(rt + s4);
            ulonglong2 ct = *(const ulonglong2*)(rt + 4 - s4);
            #pragma unroll
            for (int g = 0; g < ED; g++) {
                float vr = __shfl_sync(0xffffffffu, r2, g);
                float ve = __shfl_sync(0xffffffffu, ea, g);
                unsigned long long vv = packf2(vr, ve);
                fma2(acc[g][0], vv, at.x); fma2(acc[g][1], vv, at.y);
                fma2(acc[g][2], vv, ct.x); fma2(acc[g][3], vv, ct.y);
            }
        }

        __syncwarp();   // done reading eb (layer-1 inputs)
        #pragma unroll
        for (int g = 0; g < ED; g++) {
            float4 h;
            h.x = silu_f(lohi_sum(acc[g][0]) + sb1v.x);
            h.y = silu_f(lohi_sum(acc[g][1]) + sb1v.y);
            h.z = silu_f(lohi_sum(acc[g][2]) + sb1v.z);
            h.w = silu_f(lohi_sum(acc[g][3]) + sb1v.w);
            *(float4*)(eb + g * 256 + lane * 4) = h;
        }
        __syncwarp();

        // ---- layer 2: 128 -> 128, f32x2 ----
        #pragma unroll
        for (int g = 0; g < ED; g++)
            acc[g][0] = acc[g][1] = acc[g][2] = acc[g][3] = 0ull;

        #pragma unroll 4
        for (int k4 = 0; k4 < 32; k4++) {
            const float* r0 = sW2 + (k4 * 2) * 256 + wofs;
            ulonglong2 a0 = *(const ulonglong2*)(r0 + s4);
            ulonglong2 c0 = *(const ulonglong2*)(r0 + 4 - s4);
            ulonglong2 a1 = *(const ulonglong2*)(r0 + 256 + s4);
            ulonglong2 c1 = *(const ulonglong2*)(r0 + 256 + 4 - s4);
            #pragma unroll
            for (int g = 0; g < ED; g++) {
                ulonglong2 v = *(const ulonglong2*)(eb + g * 256 + k4 * 4);
                fma2(acc[g][0], v.x, a0.x); fma2(acc[g][1], v.x, a0.y);
                fma2(acc[g][2], v.x, c0.x); fma2(acc[g][3], v.x, c0.y);
                fma2(acc[g][0], v.y, a1.x); fma2(acc[g][1], v.y, a1.y);
                fma2(acc[g][2], v.y, c1.x); fma2(acc[g][3], v.y, c1.y);
            }
        }

        // ---- epilogue: SiLU, s-gate, gamma, scatter ----
        float psel = 0.0f;
        #pragma unroll
        for (int g = 0; g < ED; g++) {
            float sgg = __shfl_sync(0xffffffffu, sg, g);
            float4 mg;
            mg.x = silu_f(lohi_sum(acc[g][0]) + sb2v.x) * sgg;
            mg.y = silu_f(lohi_sum(acc[g][1]) + sb2v.y) * sgg;
            mg.z = silu_f(lohi_sum(acc[g][2]) + sb2v.z) * sgg;
            mg.w = silu_f(lohi_sum(acc[g][3]) + sb2v.w) * sgg;

            float p = mg.x * wcv.x + mg.y * wcv.y + mg.z * wcv.z + mg.w * wcv.w;
            #pragma unroll
            for (int o = 16; o; o >>= 1)
                p += __shfl_xor_sync(0xffffffffu, p, o);

            int okg = __shfl_sync(0xffffffffu, okflag, g);
            int dg  = __shfl_sync(0xffffffffu, dd, g);
            if (okg) red_add_v4(g_msum + (size_t)dg * 128 + lane * 4, mg);
            if (lane == g) psel = p;
        }
        if (lane < ED && have) {
            const float gam = psel + bcv;
            atomicAdd(g_coord + dd * 3 + 0, gam * dx);
            atomicAdd(g_coord + dd * 3 + 1, gam * dy);
            atomicAdd(g_coord + dd * 3 + 2, gam * dz);
            atomicAdd(g_deg + dd, 1.0f);
        }
    }
}

// ------------------------------- node ---------------------------------------
// SMEM floats: sWn1[128*256]=32768  sWn2[64*256]=16384  biases 256
//              sE[NW_N*ND*256]=8192  -> 57600 floats = 230,400 B
__global__ __launch_bounds__(TPB_N, 1)
void node_kernel(const float* __restrict__ x, const float* __restrict__ pos,
                 const float* __restrict__ Wn1, const float* __restrict__ bn1,
                 const float* __restrict__ Wn2, const float* __restrict__ bn2,
                 float* __restrict__ xout, float* __restrict__ posout,
                 int N)
{
    extern __shared__ float sm[];
    float* sW1 = sm;                  // 128 k2-rows x 256
    float* sW2 = sW1 + 128 * 256;     // 64 k2-rows x 256
    float* sb1 = sW2 + 64 * 256;
    float* sb2 = sb1 + 128;
    float* sE  = sb2 + 128;

    const int tid = threadIdx.x;
    for (int idx = tid; idx < 256 * 128; idx += TPB_N) {
        int k = idx >> 7, j = idx & 127;
        sW1[wswz(k, j)] = Wn1[idx];
    }
    for (int idx = tid; idx < 128 * 128; idx += TPB_N) {
        int k = idx >> 7, j = idx & 127;
        sW2[wswz(k, j)] = Wn2[idx];
    }
    for (int i = tid; i < 128; i += TPB_N) { sb1[i] = bn1[i]; sb2[i] = bn2[i]; }
    __syncthreads();

    const int lane = tid & 31;
    const int w    = tid >> 5;
    float* eb = sE + w * (ND * 256);

    const int wofs = lane * 8;
    const int s4   = ((lane >> 2) & 1) * 4;
    const float4 sb1v = *(const float4*)(sb1 + lane * 4);
    const float4 sb2v = *(const float4*)(sb2 + lane * 4);

    const int bstride = gridDim.x * NW_N * ND;
    for (int b0 = (blockIdx.x * NW_N + w) * ND; b0 < N; b0 += bstride) {

        int nm = b0 + lane;
        float inv = 1.0f;
        if (lane < ND && nm < N) inv = 1.0f / fmaxf(g_deg[nm], 1.0f);

        __syncwarp();
        #pragma unroll
        for (int g = 0; g < ND; g++) {
            int ng = b0 + g; if (ng >= N) ng = N - 1;
            float ig = __shfl_sync(0xffffffffu, inv, g);
            float4 xr = *(const float4*)(x + (size_t)ng * 128 + lane * 4);
            float4 ms = *(const float4*)(g_msum + (size_t)ng * 128 + lane * 4);
            ms.x *= ig; ms.y *= ig; ms.z *= ig; ms.w *= ig;
            *(float4*)(eb + g * 256 + lane * 4)       = xr;
            *(float4*)(eb + g * 256 + 128 + lane * 4) = ms;
        }
        __syncwarp();

        // layer 1: 256 -> 128, SiLU
        unsigned long long acc[ND][4];
        #pragma unroll
        for (int g = 0; g < ND; g++)
            acc[g][0] = acc[g][1] = acc[g][2] = acc[g][3] = 0ull;

        #pragma unroll 4
        for (int k4 = 0; k4 < 64; k4++) {
            const float* r0 = sW1 + (k4 * 2) * 256 + wofs;
            ulonglong2 a0 = *(const ulonglong2*)(r0 + s4);
            ulonglong2 c0 = *(const ulonglong2*)(r0 + 4 - s4);
            ulonglong2 a1 = *(const ulonglong2*)(r0 + 256 + s4);
            ulonglong2 c1 = *(const ulonglong2*)(r0 + 256 + 4 - s4);
            #pragma unroll
            for (int g = 0; g < ND; g++) {
                ulonglong2 v = *(const ulonglong2*)(eb + g * 256 + k4 * 4);
                fma2(acc[g][0], v.x, a0.x); fma2(acc[g][1], v.x, a0.y);
                fma2(acc[g][2], v.x, c0.x); fma2(acc[g][3], v.x, c0.y);
                fma2(acc[g][0], v.y, a1.x); fma2(acc[g][1], v.y, a1.y);
                fma2(acc[g][2], v.y, c1.x); fma2(acc[g][3], v.y, c1.y);
            }
        }

        __syncwarp();
        #pragma unroll
        for (int g = 0; g < ND; g++) {
            float4 h;
            h.x = silu_f(lohi_sum(acc[g][0]) + sb1v.x);
            h.y = silu_f(lohi_sum(acc[g][1]) + sb1v.y);
            h.z = silu_f(lohi_sum(acc[g][2]) + sb1v.z);
            h.w = silu_f(lohi_sum(acc[g][3]) + sb1v.w);
            *(float4*)(eb + g * 256 + lane * 4) = h;
        }
        __syncwarp();

        // layer 2: 128 -> 128, no activation
        #pragma unroll
        for (int g = 0; g < ND; g++)
            acc[g][0] = acc[g][1] = acc[g][2] = acc[g][3] = 0ull;

        #pragma unroll 4
        for (int k4 = 0; k4 < 32; k4++) {
            const float* r0 = sW2 + (k4 * 2) * 256 + wofs;
            ulonglong2 a0 = *(const ulonglong2*)(r0 + s4);
            ulonglong2 c0 = *(const ulonglong2*)(r0 + 4 - s4);
            ulonglong2 a1 = *(const ulonglong2*)(r0 + 256 + s4);
            ulonglong2 c1 = *(const ulonglong2*)(r0 + 256 + 4 - s4);
            #pragma unroll
            for (int g = 0; g < ND; g++) {
                ulonglong2 v = *(const ulonglong2*)(eb + g * 256 + k4 * 4);
                fma2(acc[g][0], v.x, a0.x); fma2(acc[g][1], v.x, a0.y);
                fma2(acc[g][2], v.x, c0.x); fma2(acc[g][3], v.x, c0.y);
                fma2(acc[g][0], v.y, a1.x); fma2(acc[g][1], v.y, a1.y);
                fma2(acc[g][2], v.y, c1.x); fma2(acc[g][3], v.y, c1.y);
            }
        }

        #pragma unroll
        for (int g = 0; g < ND; g++) {
            int ng = b0 + g;
            if (ng < N) {
                float4 o;
                o.x = lohi_sum(acc[g][0]) + sb2v.x;
                o.y = lohi_sum(acc[g][1]) + sb2v.y;
                o.z = lohi_sum(acc[g][2]) + sb2v.z;
                o.w = lohi_sum(acc[g][3]) + sb2v.w;
                *(float4*)(xout + (size_t)ng * 128 + lane * 4) = o;
                float ig = __shfl_sync(0xffffffffu, inv, g);
                if (lane < 3)
                    posout[ng * 3 + lane] =
                        pos[ng * 3 + lane] + g_coord[ng * 3 + lane] * ig;
            }
        }
    }
}

// ------------------------------- launch --------------------------------------
extern "C" void kernel_launch(void* const* d_in, const int* in_sizes, int n_in,
                              void* d_out, int out_size) {
    const float* x     = (const float*)d_in[0];
    const float* pos   = (const float*)d_in[1];
    const void*  ei    = d_in[2];
    const float* eattr = (const float*)d_in[3];
    const float* s     = (const float*)d_in[4];
    const float* We1   = (const float*)d_in[5];
    const float* be1   = (const float*)d_in[6];
    const float* We2   = (const float*)d_in[7];
    const float* be2   = (const float*)d_in[8];
    const float* Wn1   = (const float*)d_in[9];
    const float* bn1   = (const float*)d_in[10];
    const float* Wn2   = (const float*)d_in[11];
    const float* bn2   = (const float*)d_in[12];
    const float* Wc    = (const float*)d_in[13];
    const float* bc    = (const float*)d_in[14];

    const int N = in_sizes[0] / 128;
    const int E = in_sizes[2] / 2;

    float* xout   = (float*)d_out;
    float* posout = (float*)d_out + (size_t)N * 128;

    int dev = 0, nsm = 148;
    cudaGetDevice(&dev);
    cudaDeviceGetAttribute(&nsm, cudaDevAttrMultiProcessorCount, dev);

    const size_t smem_edge = (size_t)(129 * 256 + 64 * 256 + 3 * 128 +
                                      NW_E * ED * 256) * sizeof(float);   // 231,936
    const size_t smem_node = (size_t)(128 * 256 + 64 * 256 + 2 * 128 +
                                      NW_N * ND * 256) * sizeof(float);   // 230,400

    cudaFuncSetAttribute(edge_kernel, cudaFuncAttributeMaxDynamicSharedMemorySize,
                         (int)smem_edge);
    cudaFuncSetAttribute(node_kernel, cudaFuncAttributeMaxDynamicSharedMemorySize,
                         (int)smem_node);

    zero_kernel<<<256, 256>>>(N);
    detect_kernel<<<16, 256>>>((const unsigned int*)ei, E);
    edge_kernel<<<nsm, TPB_E, smem_edge>>>(x, pos,
                                           (const int*)ei, (const long long*)ei,
                                           eattr, s,
                                           We1, be1, We2, be2, Wc, bc, E, N);
    node_kernel<<<nsm, TPB_N, smem_node>>>(x, pos, Wn1, bn1, Wn2, bn2,
                                           xout, posout, N);
}

// round 12
// speedup vs baseline: 1.4929x; 1.1866x over previous
#include <cuda_runtime.h>
#include <cuda_bf16.h>
#include <cstdint>

// ---------------------------------------------------------------------------
// EGNN layer, fused, f32x2 (FFMA2) GEMV path, phase-split activation staging.
//   zero_kernel:   clear accumulators + dtype-detect flag
//   detect_kernel: sniff whether edge_index is int32 or int64
//   edge_kernel:   8 warps/block (2 per SMSP), 8 edges/warp. Layer 1 is
//                  consumed in two phases (x[dst] rows 0..127, then x[src]
//                  rows 128..255) over a 128-float/edge buffer so the whole
//                  thing fits in 227KB SMEM at 256 threads.
//   node_kernel:   8 warps/block, 8 nodes/warp, same phase-split scheme.
// Weights stored k-pair interleaved with a 16B XOR swizzle -> conflict-free
// warp-wide LDS.128; accumulation is k-pairwise in f32x2 lanes.
// ---------------------------------------------------------------------------

#define NMAX 50048

#define NW_E 8
#define TPB_E (NW_E * 32)   // 256
#define ED 8                // edges per warp

#define NW_N 8
#define TPB_N (NW_N * 32)   // 256
#define ND 8                // nodes per warp

__device__ __align__(16) float g_msum[(size_t)NMAX * 128];
__device__ __align__(16) float g_coord[(size_t)NMAX * 3];
__device__ __align__(16) float g_deg[NMAX];
__device__ int g_or;        // 0 => indices are int64, nonzero => int32

__device__ __forceinline__ float silu_f(float v) {
    return __fdividef(v, 1.0f + __expf(-v));
}

__device__ __forceinline__ void red_add_v4(float* addr, float4 v) {
    asm volatile("red.global.add.v4.f32 [%0], {%1,%2,%3,%4};"
                 :: "l"(addr), "f"(v.x), "f"(v.y), "f"(v.z), "f"(v.w)
                 : "memory");
}

__device__ __forceinline__ void fma2(unsigned long long& a,
                                     unsigned long long v,
                                     unsigned long long w) {
    asm("fma.rn.f32x2 %0, %1, %2, %0;" : "+l"(a) : "l"(v), "l"(w));
}
__device__ __forceinline__ float lohi_sum(unsigned long long a) {
    float lo, hi;
    asm("mov.b64 {%0,%1}, %2;" : "=f"(lo), "=f"(hi) : "l"(a));
    return lo + hi;
}
__device__ __forceinline__ unsigned long long packf2(float lo, float hi) {
    unsigned long long r;
    asm("mov.b64 %0, {%1,%2};" : "=l"(r) : "f"(lo), "f"(hi));
    return r;
}

// Swizzled index for k-pair interleaved weight storage.
// Logical W[k][j] (j = 0..127). Row = k/2 (256 floats). Lane L = (j*2+(k&1))/8
// owns a 32B group (4 outputs x 2 k); the two 16B chunks of each group are
// swapped when (L>>2)&1 so warp-wide LDS.128 is conflict-free.
__device__ __forceinline__ int wswz(int k, int j) {
    int k2 = k >> 1, p = k & 1;
    int col = j * 2 + p;             // 0..255
    int L = col >> 3;                // owning lane
    int o = col & 7;
    int c = o >> 2;                  // chunk 0/1
    int pos = o & 3;
    return k2 * 256 + (L * 2 + (c ^ ((L >> 2) & 1))) * 4 + pos;
}

// One k4 step (2 k-pairs = 4 k values) of the packed GEMV for NA accumulators.
template<int NA>
__device__ __forceinline__ void gemv_step(const float* __restrict__ wrow,
                                          int s4,
                                          const float* __restrict__ act,
                                          int actStride, int kofs,
                                          unsigned long long (*acc)[4]) {
    ulonglong2 a0 = *(const ulonglong2*)(wrow + s4);
    ulonglong2 c0 = *(const ulonglong2*)(wrow + 4 - s4);
    ulonglong2 a1 = *(const ulonglong2*)(wrow + 256 + s4);
    ulonglong2 c1 = *(const ulonglong2*)(wrow + 256 + 4 - s4);
    #pragma unroll
    for (int g = 0; g < NA; g++) {
        ulonglong2 v = *(const ulonglong2*)(act + g * actStride + kofs);
        fma2(acc[g][0], v.x, a0.x); fma2(acc[g][1], v.x, a0.y);
        fma2(acc[g][2], v.x, c0.x); fma2(acc[g][3], v.x, c0.y);
        fma2(acc[g][0], v.y, a1.x); fma2(acc[g][1], v.y, a1.y);
        fma2(acc[g][2], v.y, c1.x); fma2(acc[g][3], v.y, c1.y);
    }
}

// ------------------------------- zero ---------------------------------------
__global__ void zero_kernel(int n) {
    int i = blockIdx.x * blockDim.x + threadIdx.x;
    int stride = gridDim.x * blockDim.x;
    if (i == 0) g_or = 0;
    int total = n * 128;
    for (int j = i; j < total; j += stride) g_msum[j] = 0.0f;
    for (int j = i; j < n * 3; j += stride) g_coord[j] = 0.0f;
    for (int j = i; j < n;     j += stride) g_deg[j]   = 0.0f;
}

// ------------------------------- detect --------------------------------------
__global__ void detect_kernel(const unsigned int* w, int E) {
    unsigned acc = 0;
    int lim = E < 8192 ? E : 8192;
    for (int i = blockIdx.x * blockDim.x + threadIdx.x; i < lim;
         i += gridDim.x * blockDim.x)
        acc |= w[2 * i + 1];
    if (acc) atomicOr(&g_or, 1);
}

// ------------------------------- edge ---------------------------------------
// SMEM floats: sW1[129*256]=33024  sW2[64*256]=16384  sWc/sb1/sb2[384]
//              sE[NW_E*ED*128]=8192   -> 57984 floats = 231,936 B
__global__ __launch_bounds__(TPB_E, 1)
void edge_kernel(const float* __restrict__ x, const float* __restrict__ pos,
                 const int* __restrict__ ei32, const long long* __restrict__ ei64,
                 const float* __restrict__ eattr, const float* __restrict__ s,
                 const float* __restrict__ We1, const float* __restrict__ be1,
                 const float* __restrict__ We2, const float* __restrict__ be2,
                 const float* __restrict__ Wc,  const float* __restrict__ bc,
                 int E, int Nn)
{
    extern __shared__ float sm[];
    float* sW1 = sm;                  // 129 k2-rows x 256
    float* sW2 = sW1 + 129 * 256;     // 64 k2-rows x 256
    float* sWc = sW2 + 64 * 256;
    float* sb1 = sWc + 128;
    float* sb2 = sb1 + 128;
    float* sE  = sb2 + 128;

    const int tid = threadIdx.x;
    for (int idx = tid; idx < 258 * 128; idx += TPB_E) {
        int k = idx >> 7, j = idx & 127;
        sW1[wswz(k, j)] = We1[idx];
    }
    for (int idx = tid; idx < 128 * 128; idx += TPB_E) {
        int k = idx >> 7, j = idx & 127;
        sW2[wswz(k, j)] = We2[idx];
    }
    for (int i = tid; i < 128; i += TPB_E) {
        sWc[i] = Wc[i]; sb1[i] = be1[i]; sb2[i] = be2[i];
    }
    __syncthreads();

    const bool idx64 = (g_or == 0);
    const float bcv  = bc[0];
    const int lane   = tid & 31;
    const int w      = tid >> 5;
    float* eb = sE + w * (ED * 128);

    const int wofs = lane * 8;
    const int s4   = ((lane >> 2) & 1) * 4;
    const float4 sb1v = *(const float4*)(sb1 + lane * 4);
    const float4 sb2v = *(const float4*)(sb2 + lane * 4);
    const float4 wcv  = *(const float4*)(sWc + lane * 4);

    const long long bstride = (long long)gridDim.x * NW_E * ED;
    for (long long b0 = ((long long)blockIdx.x * NW_E + w) * ED;
         b0 < E; b0 += bstride) {

        // ---- lane-distributed per-edge metadata (lane g owns edge b0+g) ----
        long long e = b0 + lane;
        bool have = (lane < ED) && (e < (long long)E);
        int ss = 0, dd = 0;
        if (have) {
            if (idx64) { ss = (int)ei64[e]; dd = (int)ei64[E + e]; }
            else       { ss = ei32[e];      dd = ei32[E + e]; }
            if ((unsigned)ss >= (unsigned)Nn || (unsigned)dd >= (unsigned)Nn) {
                have = false; ss = 0; dd = 0;
            }
        }
        float dx = 0.f, dy = 0.f, dz = 0.f, r2 = 0.f, ea = 0.f, sg = 0.f;
        if (lane < ED) {
            dx = pos[dd * 3 + 0] - pos[ss * 3 + 0];
            dy = pos[dd * 3 + 1] - pos[ss * 3 + 1];
            dz = pos[dd * 3 + 2] - pos[ss * 3 + 2];
            r2 = dx * dx + dy * dy + dz * dz;
            ea = have ? eattr[e] : 0.0f;
            sg = s[ss];
        }
        const int okflag = have ? 1 : 0;

        unsigned long long acc[ED][4];
        #pragma unroll
        for (int g = 0; g < ED; g++)
            acc[g][0] = acc[g][1] = acc[g][2] = acc[g][3] = 0ull;

        // ---- layer 1 phase A: rows 0..127 with x[dst] ----
        __syncwarp();
        #pragma unroll
        for (int g = 0; g < ED; g++) {
            int dg = __shfl_sync(0xffffffffu, dd, g);
            *(float4*)(eb + g * 128 + lane * 4) =
                *(const float4*)(x + (size_t)dg * 128 + lane * 4);
        }
        __syncwarp();
        #pragma unroll 4
        for (int k4 = 0; k4 < 32; k4++)
            gemv_step<ED>(sW1 + (k4 * 2) * 256 + wofs, s4, eb, 128, k4 * 4, acc);

        // ---- layer 1 phase B: rows 128..255 with x[src] ----
        __syncwarp();
        #pragma unroll
        for (int g = 0; g < ED; g++) {
            int sgi = __shfl_sync(0xffffffffu, ss, g);
            *(float4*)(eb + g * 128 + lane * 4) =
                *(const float4*)(x + (size_t)sgi * 128 + lane * 4);
        }
        __syncwarp();
        #pragma unroll 4
        for (int k4 = 0; k4 < 32; k4++)
            gemv_step<ED>(sW1 + ((k4 + 32) * 2) * 256 + wofs, s4, eb, 128, k4 * 4, acc);

        {   // tail k-pair (k=256: r2, k=257: edge_attr) = k2 row 128
            const float* rt = sW1 + 128 * 256 + wofs;
            ulonglong2 at = *(const ulonglong2*)(rt + s4);
            ulonglong2 ct = *(const ulonglong2*)(rt + 4 - s4);
            #pragma unroll
            for (int g = 0; g < ED; g++) {
                float vr = __shfl_sync(0xffffffffu, r2, g);
                float ve = __shfl_sync(0xffffffffu, ea, g);
                unsigned long long vv = packf2(vr, ve);
                fma2(acc[g][0], vv, at.x); fma2(acc[g][1], vv, at.y);
                fma2(acc[g][2], vv, ct.x); fma2(acc[g][3], vv, ct.y);
            }
        }

        // ---- SiLU, stage h, layer 2 ----
        __syncwarp();
        #pragma unroll
        for (int g = 0; g < ED; g++) {
            float4 h;
            h.x = silu_f(lohi_sum(acc[g][0]) + sb1v.x);
            h.y = silu_f(lohi_sum(acc[g][1]) + sb1v.y);
            h.z = silu_f(lohi_sum(acc[g][2]) + sb1v.z);
            h.w = silu_f(lohi_sum(acc[g][3]) + sb1v.w);
            *(float4*)(eb + g * 128 + lane * 4) = h;
            acc[g][0] = acc[g][1] = acc[g][2] = acc[g][3] = 0ull;
        }
        __syncwarp();

        #pragma unroll 4
        for (int k4 = 0; k4 < 32; k4++)
            gemv_step<ED>(sW2 + (k4 * 2) * 256 + wofs, s4, eb, 128, k4 * 4, acc);

        // ---- epilogue: SiLU, s-gate, gamma, scatter ----
        float psel = 0.0f;
        #pragma unroll
        for (int g = 0; g < ED; g++) {
            float sgg = __shfl_sync(0xffffffffu, sg, g);
            float4 mg;
            mg.x = silu_f(lohi_sum(acc[g][0]) + sb2v.x) * sgg;
            mg.y = silu_f(lohi_sum(acc[g][1]) + sb2v.y) * sgg;
            mg.z = silu_f(lohi_sum(acc[g][2]) + sb2v.z) * sgg;
            mg.w = silu_f(lohi_sum(acc[g][3]) + sb2v.w) * sgg;

            float p = mg.x * wcv.x + mg.y * wcv.y + mg.z * wcv.z + mg.w * wcv.w;
            #pragma unroll
            for (int o = 16; o; o >>= 1)
                p += __shfl_xor_sync(0xffffffffu, p, o);

            int okg = __shfl_sync(0xffffffffu, okflag, g);
            int dg  = __shfl_sync(0xffffffffu, dd, g);
            if (okg) red_add_v4(g_msum + (size_t)dg * 128 + lane * 4, mg);
            if (lane == g) psel = p;
        }
        if (lane < ED && have) {
            const float gam = psel + bcv;
            atomicAdd(g_coord + dd * 3 + 0, gam * dx);
            atomicAdd(g_coord + dd * 3 + 1, gam * dy);
            atomicAdd(g_coord + dd * 3 + 2, gam * dz);
            atomicAdd(g_deg + dd, 1.0f);
        }
    }
}

// ------------------------------- node ---------------------------------------
// SMEM floats: sWn1[128*256]=32768  sWn2[64*256]=16384  biases 256
//              sE[NW_N*ND*128]=8192  -> 57600 floats = 230,400 B
__global__ __launch_bounds__(TPB_N, 1)
void node_kernel(const float* __restrict__ x, const float* __restrict__ pos,
                 const float* __restrict__ Wn1, const float* __restrict__ bn1,
                 const float* __restrict__ Wn2, const float* __restrict__ bn2,
                 float* __restrict__ xout, float* __restrict__ posout,
                 int N)
{
    extern __shared__ float sm[];
    float* sW1 = sm;                  // 128 k2-rows x 256
    float* sW2 = sW1 + 128 * 256;     // 64 k2-rows x 256
    float* sb1 = sW2 + 64 * 256;
    float* sb2 = sb1 + 128;
    float* sE  = sb2 + 128;

    const int tid = threadIdx.x;
    for (int idx = tid; idx < 256 * 128; idx += TPB_N) {
        int k = idx >> 7, j = idx & 127;
        sW1[wswz(k, j)] = Wn1[idx];
    }
    for (int idx = tid; idx < 128 * 128; idx += TPB_N) {
        int k = idx >> 7, j = idx & 127;
        sW2[wswz(k, j)] = Wn2[idx];
    }
    for (int i = tid; i < 128; i += TPB_N) { sb1[i] = bn1[i]; sb2[i] = bn2[i]; }
    __syncthreads();

    const int lane = tid & 31;
    const int w    = tid >> 5;
    float* eb = sE + w * (ND * 128);

    const int wofs = lane * 8;
    const int s4   = ((lane >> 2) & 1) * 4;
    const float4 sb1v = *(const float4*)(sb1 + lane * 4);
    const float4 sb2v = *(const float4*)(sb2 + lane * 4);

    const int bstride = gridDim.x * NW_N * ND;
    for (int b0 = (blockIdx.x * NW_N + w) * ND; b0 < N; b0 += bstride) {

        int nm = b0 + lane;
        float inv = 1.0f;
        if (lane < ND && nm < N) inv = 1.0f / fmaxf(g_deg[nm], 1.0f);

        unsigned long long acc[ND][4];
        #pragma unroll
        for (int g = 0; g < ND; g++)
            acc[g][0] = acc[g][1] = acc[g][2] = acc[g][3] = 0ull;

        // ---- layer 1 phase A: rows 0..127 with x ----
        __syncwarp();
        #pragma unroll
        for (int g = 0; g < ND; g++) {
            int ng = b0 + g; if (ng >= N) ng = N - 1;
            *(float4*)(eb + g * 128 + lane * 4) =
                *(const float4*)(x + (size_t)ng * 128 + lane * 4);
        }
        __syncwarp();
        #pragma unroll 4
        for (int k4 = 0; k4 < 32; k4++)
            gemv_step<ND>(sW1 + (k4 * 2) * 256 + wofs, s4, eb, 128, k4 * 4, acc);

        // ---- layer 1 phase B: rows 128..255 with m_sum/deg ----
        __syncwarp();
        #pragma unroll
        for (int g = 0; g < ND; g++) {
            int ng = b0 + g; if (ng >= N) ng = N - 1;
            float ig = __shfl_sync(0xffffffffu, inv, g);
            float4 ms = *(const float4*)(g_msum + (size_t)ng * 128 + lane * 4);
            ms.x *= ig; ms.y *= ig; ms.z *= ig; ms.w *= ig;
            *(float4*)(eb + g * 128 + lane * 4) = ms;
        }
        __syncwarp();
        #pragma unroll 4
        for (int k4 = 0; k4 < 32; k4++)
            gemv_step<ND>(sW1 + ((k4 + 32) * 2) * 256 + wofs, s4, eb, 128, k4 * 4, acc);

        // ---- SiLU, stage h, layer 2 ----
        __syncwarp();
        #pragma unroll
        for (int g = 0; g < ND; g++) {
            float4 h;
            h.x = silu_f(lohi_sum(acc[g][0]) + sb1v.x);
            h.y = silu_f(lohi_sum(acc[g][1]) + sb1v.y);
            h.z = silu_f(lohi_sum(acc[g][2]) + sb1v.z);
            h.w = silu_f(lohi_sum(acc[g][3]) + sb1v.w);
            *(float4*)(eb + g * 128 + lane * 4) = h;
            acc[g][0] = acc[g][1] = acc[g][2] = acc[g][3] = 0ull;
        }
        __syncwarp();

        #pragma unroll 4
        for (int k4 = 0; k4 < 32; k4++)
            gemv_step<ND>(sW2 + (k4 * 2) * 256 + wofs, s4, eb, 128, k4 * 4, acc);

        #pragma unroll
        for (int g = 0; g < ND; g++) {
            int ng = b0 + g;
            if (ng < N) {
                float4 o;
                o.x = lohi_sum(acc[g][0]) + sb2v.x;
                o.y = lohi_sum(acc[g][1]) + sb2v.y;
                o.z = lohi_sum(acc[g][2]) + sb2v.z;
                o.w = lohi_sum(acc[g][3]) + sb2v.w;
                *(float4*)(xout + (size_t)ng * 128 + lane * 4) = o;
                float ig = __shfl_sync(0xffffffffu, inv, g);
                if (lane < 3)
                    posout[ng * 3 + lane] =
                        pos[ng * 3 + lane] + g_coord[ng * 3 + lane] * ig;
            }
        }
    }
}

// ------------------------------- launch --------------------------------------
extern "C" void kernel_launch(void* const* d_in, const int* in_sizes, int n_in,
                              void* d_out, int out_size) {
    const float* x     = (const float*)d_in[0];
    const float* pos   = (const float*)d_in[1];
    const void*  ei    = d_in[2];
    const float* eattr = (const float*)d_in[3];
    const float* s     = (const float*)d_in[4];
    const float* We1   = (const float*)d_in[5];
    const float* be1   = (const float*)d_in[6];
    const float* We2   = (const float*)d_in[7];
    const float* be2   = (const float*)d_in[8];
    const float* Wn1   = (const float*)d_in[9];
    const float* bn1   = (const float*)d_in[10];
    const float* Wn2   = (const float*)d_in[11];
    const float* bn2   = (const float*)d_in[12];
    const float* Wc    = (const float*)d_in[13];
    const float* bc    = (const float*)d_in[14];

    const int N = in_sizes[0] / 128;
    const int E = in_sizes[2] / 2;

    float* xout   = (float*)d_out;
    float* posout = (float*)d_out + (size_t)N * 128;

    int dev = 0, nsm = 148;
    cudaGetDevice(&dev);
    cudaDeviceGetAttribute(&nsm, cudaDevAttrMultiProcessorCount, dev);

    const size_t smem_edge = (size_t)(129 * 256 + 64 * 256 + 3 * 128 +
                                      NW_E * ED * 128) * sizeof(float);   // 231,936
    const size_t smem_node = (size_t)(128 * 256 + 64 * 256 + 2 * 128 +
                                      NW_N * ND * 128) * sizeof(float);   // 230,400

    cudaFuncSetAttribute(edge_kernel, cudaFuncAttributeMaxDynamicSharedMemorySize,
                         (int)smem_edge);
    cudaFuncSetAttribute(node_kernel, cudaFuncAttributeMaxDynamicSharedMemorySize,
                         (int)smem_node);

    zero_kernel<<<256, 256>>>(N);
    detect_kernel<<<16, 256>>>((const unsigned int*)ei, E);
    edge_kernel<<<nsm, TPB_E, smem_edge>>>(x, pos,
                                           (const int*)ei, (const long long*)ei,
                                           eattr, s,
                                           We1, be1, We2, be2, Wc, bc, E, N);
    node_kernel<<<nsm, TPB_N, smem_node>>>(x, pos, Wn1, bn1, Wn2, bn2,
                                           xout, posout, N);
}

// round 13
// speedup vs baseline: 3.0951x; 2.0732x over previous
#include <cuda_runtime.h>
#include <cuda_bf16.h>
#include <cstdint>

// ---------------------------------------------------------------------------
// EGNN layer, fused, f32x2 (FFMA2) GEMV path + algebraic layer-1 hoisting.
//   Layer 1 of the edge MLP is linear in the gathered features:
//     e_in @ W_e1 = x[dst]@W1a + x[src]@W1b + r2*w_r2 + ea*w_ea
//   so P = x@W1a and Q = x@W1b are precomputed per NODE (pre_kernel), and the
//   per-EDGE layer 1 is just silu(P[dst]+Q[src]+r2*w_r2+ea*w_ea+b1).
//   edge_kernel then only runs the 128-deep layer-2 GEMV + epilogue.
// Weights stored k-pair interleaved with a 16B XOR swizzle -> conflict-free
// warp-wide LDS.128; accumulation is k-pairwise in f32x2 lanes.
// ---------------------------------------------------------------------------

#define NMAX 50048

#define NW_P 8
#define TPB_P (NW_P * 32)   // 256
#define ND_P 8              // nodes per warp (pre)

#define NW_E 12
#define TPB_E (NW_E * 32)   // 384
#define ED 8                // edges per warp

#define NW_N 8
#define TPB_N (NW_N * 32)   // 256
#define ND 8                // nodes per warp

__device__ __align__(16) float g_msum[(size_t)NMAX * 128];
__device__ __align__(16) float g_coord[(size_t)NMAX * 3];
__device__ __align__(16) float g_deg[NMAX];
__device__ __align__(16) float g_P[(size_t)NMAX * 128];
__device__ __align__(16) float g_Q[(size_t)NMAX * 128];
__device__ int g_or;        // 0 => indices are int64, nonzero => int32

__device__ __forceinline__ float silu_f(float v) {
    return __fdividef(v, 1.0f + __expf(-v));
}

__device__ __forceinline__ void red_add_v4(float* addr, float4 v) {
    asm volatile("red.global.add.v4.f32 [%0], {%1,%2,%3,%4};"
                 :: "l"(addr), "f"(v.x), "f"(v.y), "f"(v.z), "f"(v.w)
                 : "memory");
}

__device__ __forceinline__ void fma2(unsigned long long& a,
                                     unsigned long long v,
                                     unsigned long long w) {
    asm("fma.rn.f32x2 %0, %1, %2, %0;" : "+l"(a) : "l"(v), "l"(w));
}
__device__ __forceinline__ float lohi_sum(unsigned long long a) {
    float lo, hi;
    asm("mov.b64 {%0,%1}, %2;" : "=f"(lo), "=f"(hi) : "l"(a));
    return lo + hi;
}

// Swizzled index for k-pair interleaved weight storage (see round 11/12).
// acc[g][i] ends up holding output j = lane*4 + i.
__device__ __forceinline__ int wswz(int k, int j) {
    int k2 = k >> 1, p = k & 1;
    int col = j * 2 + p;             // 0..255
    int L = col >> 3;                // owning lane
    int o = col & 7;
    int c = o >> 2;                  // chunk 0/1
    int pos = o & 3;
    return k2 * 256 + (L * 2 + (c ^ ((L >> 2) & 1))) * 4 + pos;
}

// One k4 step (2 k-pairs = 4 k values) of the packed GEMV for NA accumulators.
template<int NA>
__device__ __forceinline__ void gemv_step(const float* __restrict__ wrow,
                                          int s4,
                                          const float* __restrict__ act,
                                          int actStride, int kofs,
                                          unsigned long long (*acc)[4]) {
    ulonglong2 a0 = *(const ulonglong2*)(wrow + s4);
    ulonglong2 c0 = *(const ulonglong2*)(wrow + 4 - s4);
    ulonglong2 a1 = *(const ulonglong2*)(wrow + 256 + s4);
    ulonglong2 c1 = *(const ulonglong2*)(wrow + 256 + 4 - s4);
    #pragma unroll
    for (int g = 0; g < NA; g++) {
        ulonglong2 v = *(const ulonglong2*)(act + g * actStride + kofs);
        fma2(acc[g][0], v.x, a0.x); fma2(acc[g][1], v.x, a0.y);
        fma2(acc[g][2], v.x, c0.x); fma2(acc[g][3], v.x, c0.y);
        fma2(acc[g][0], v.y, a1.x); fma2(acc[g][1], v.y, a1.y);
        fma2(acc[g][2], v.y, c1.x); fma2(acc[g][3], v.y, c1.y);
    }
}

// ------------------------------- zero ---------------------------------------
__global__ void zero_kernel(int n) {
    int i = blockIdx.x * blockDim.x + threadIdx.x;
    int stride = gridDim.x * blockDim.x;
    if (i == 0) g_or = 0;
    int total = n * 128;
    for (int j = i; j < total; j += stride) g_msum[j] = 0.0f;
    for (int j = i; j < n * 3; j += stride) g_coord[j] = 0.0f;
    for (int j = i; j < n;     j += stride) g_deg[j]   = 0.0f;
}

// ------------------------------- detect --------------------------------------
__global__ void detect_kernel(const unsigned int* w, int E) {
    unsigned acc = 0;
    int lim = E < 8192 ? E : 8192;
    for (int i = blockIdx.x * blockDim.x + threadIdx.x; i < lim;
         i += gridDim.x * blockDim.x)
        acc |= w[2 * i + 1];
    if (acc) atomicOr(&g_or, 1);
}

// ------------------------------- pre ----------------------------------------
// P = x @ W1[0:128,:],  Q = x @ W1[128:256,:]   (no bias)
// SMEM floats: sWa[64*256]=16384  sWb[64*256]=16384  eb[NW_P*ND_P*128]=8192
//              -> 40,960 floats = 163,840 B
__global__ __launch_bounds__(TPB_P, 1)
void pre_kernel(const float* __restrict__ x, const float* __restrict__ We1,
                int N)
{
    extern __shared__ float sm[];
    float* sWa = sm;
    float* sWb = sWa + 64 * 256;
    float* sE  = sWb + 64 * 256;

    const int tid = threadIdx.x;
    for (int idx = tid; idx < 128 * 128; idx += TPB_P) {
        int k = idx >> 7, j = idx & 127;
        int d = wswz(k, j);
        sWa[d] = We1[idx];
        sWb[d] = We1[128 * 128 + idx];
    }
    __syncthreads();

    const int lane = tid & 31;
    const int w    = tid >> 5;
    float* eb = sE + w * (ND_P * 128);

    const int wofs = lane * 8;
    const int s4   = ((lane >> 2) & 1) * 4;

    const int bstride = gridDim.x * NW_P * ND_P;
    for (int b0 = (blockIdx.x * NW_P + w) * ND_P; b0 < N; b0 += bstride) {
        __syncwarp();
        #pragma unroll
        for (int g = 0; g < ND_P; g++) {
            int ng = b0 + g; if (ng >= N) ng = N - 1;
            *(float4*)(eb + g * 128 + lane * 4) =
                *(const float4*)(x + (size_t)ng * 128 + lane * 4);
        }
        __syncwarp();

        unsigned long long acc[ND_P][4];
        #pragma unroll
        for (int g = 0; g < ND_P; g++)
            acc[g][0] = acc[g][1] = acc[g][2] = acc[g][3] = 0ull;
        #pragma unroll 4
        for (int k4 = 0; k4 < 32; k4++)
            gemv_step<ND_P>(sWa + (k4 * 2) * 256 + wofs, s4, eb, 128, k4 * 4, acc);
        #pragma unroll
        for (int g = 0; g < ND_P; g++) {
            int ng = b0 + g;
            if (ng < N) {
                float4 o;
                o.x = lohi_sum(acc[g][0]); o.y = lohi_sum(acc[g][1]);
                o.z = lohi_sum(acc[g][2]); o.w = lohi_sum(acc[g][3]);
                *(float4*)(g_P + (size_t)ng * 128 + lane * 4) = o;
            }
            acc[g][0] = acc[g][1] = acc[g][2] = acc[g][3] = 0ull;
        }

        #pragma unroll 4
        for (int k4 = 0; k4 < 32; k4++)
            gemv_step<ND_P>(sWb + (k4 * 2) * 256 + wofs, s4, eb, 128, k4 * 4, acc);
        #pragma unroll
        for (int g = 0; g < ND_P; g++) {
            int ng = b0 + g;
            if (ng < N) {
                float4 o;
                o.x = lohi_sum(acc[g][0]); o.y = lohi_sum(acc[g][1]);
                o.z = lohi_sum(acc[g][2]); o.w = lohi_sum(acc[g][3]);
                *(float4*)(g_Q + (size_t)ng * 128 + lane * 4) = o;
            }
        }
    }
}

// ------------------------------- edge ---------------------------------------
// SMEM floats: sW2[64*256]=16384  sWc/sb2/sb1/swr/swe[640]
//              eb[NW_E*ED*128]=12288  -> 29,312 floats = 117,248 B
__global__ __launch_bounds__(TPB_E, 1)
void edge_kernel(const float* __restrict__ pos,
                 const int* __restrict__ ei32, const long long* __restrict__ ei64,
                 const float* __restrict__ eattr, const float* __restrict__ s,
                 const float* __restrict__ We1, const float* __restrict__ be1,
                 const float* __restrict__ We2, const float* __restrict__ be2,
                 const float* __restrict__ Wc,  const float* __restrict__ bc,
                 int E, int Nn)
{
    extern __shared__ float sm[];
    float* sW2 = sm;                  // 64 k2-rows x 256
    float* sWc = sW2 + 64 * 256;
    float* sb2 = sWc + 128;
    float* sb1 = sb2 + 128;
    float* swr = sb1 + 128;           // W1 row 256 (r2 weights)
    float* swe = swr + 128;           // W1 row 257 (edge_attr weights)
    float* sE  = swe + 128;

    const int tid = threadIdx.x;
    for (int idx = tid; idx < 128 * 128; idx += TPB_E) {
        int k = idx >> 7, j = idx & 127;
        sW2[wswz(k, j)] = We2[idx];
    }
    for (int i = tid; i < 128; i += TPB_E) {
        sWc[i] = Wc[i]; sb2[i] = be2[i]; sb1[i] = be1[i];
        swr[i] = We1[256 * 128 + i];
        swe[i] = We1[257 * 128 + i];
    }
    __syncthreads();

    const bool idx64 = (g_or == 0);
    const float bcv  = bc[0];
    const int lane   = tid & 31;
    const int w      = tid >> 5;
    float* eb = sE + w * (ED * 128);

    const int wofs = lane * 8;
    const int s4   = ((lane >> 2) & 1) * 4;
    const float4 sb2v = *(const float4*)(sb2 + lane * 4);
    const float4 sb1v = *(const float4*)(sb1 + lane * 4);
    const float4 wrv  = *(const float4*)(swr + lane * 4);
    const float4 wev  = *(const float4*)(swe + lane * 4);
    const float4 wcv  = *(const float4*)(sWc + lane * 4);

    const long long bstride = (long long)gridDim.x * NW_E * ED;
    for (long long b0 = ((long long)blockIdx.x * NW_E + w) * ED;
         b0 < E; b0 += bstride) {

        // ---- lane-distributed per-edge metadata (lane g owns edge b0+g) ----
        long long e = b0 + lane;
        bool have = (lane < ED) && (e < (long long)E);
        int ss = 0, dd = 0;
        if (have) {
            if (idx64) { ss = (int)ei64[e]; dd = (int)ei64[E + e]; }
            else       { ss = ei32[e];      dd = ei32[E + e]; }
            if ((unsigned)ss >= (unsigned)Nn || (unsigned)dd >= (unsigned)Nn) {
                have = false; ss = 0; dd = 0;
            }
        }
        float dx = 0.f, dy = 0.f, dz = 0.f, r2 = 0.f, ea = 0.f, sg = 0.f;
        if (lane < ED) {
            dx = pos[dd * 3 + 0] - pos[ss * 3 + 0];
            dy = pos[dd * 3 + 1] - pos[ss * 3 + 1];
            dz = pos[dd * 3 + 2] - pos[ss * 3 + 2];
            r2 = dx * dx + dy * dy + dz * dz;
            ea = have ? eattr[e] : 0.0f;
            sg = s[ss];
        }
        const int okflag = have ? 1 : 0;

        // ---- layer-1 via hoisting: h = silu(P[dst] + Q[src] + r2*wr + ea*we + b1)
        __syncwarp();
        #pragma unroll
        for (int g = 0; g < ED; g++) {
            int dg  = __shfl_sync(0xffffffffu, dd, g);
            int sgi = __shfl_sync(0xffffffffu, ss, g);
            float r2g = __shfl_sync(0xffffffffu, r2, g);
            float eag = __shfl_sync(0xffffffffu, ea, g);
            float4 pv = *(const float4*)(g_P + (size_t)dg  * 128 + lane * 4);
            float4 qv = *(const float4*)(g_Q + (size_t)sgi * 128 + lane * 4);
            float4 h;
            h.x = silu_f(fmaf(r2g, wrv.x, fmaf(eag, wev.x, pv.x + qv.x + sb1v.x)));
            h.y = silu_f(fmaf(r2g, wrv.y, fmaf(eag, wev.y, pv.y + qv.y + sb1v.y)));
            h.z = silu_f(fmaf(r2g, wrv.z, fmaf(eag, wev.z, pv.z + qv.z + sb1v.z)));
            h.w = silu_f(fmaf(r2g, wrv.w, fmaf(eag, wev.w, pv.w + qv.w + sb1v.w)));
            *(float4*)(eb + g * 128 + lane * 4) = h;
        }
        __syncwarp();

        // ---- layer 2: 128 -> 128, f32x2 ----
        unsigned long long acc[ED][4];
        #pragma unroll
        for (int g = 0; g < ED; g++)
            acc[g][0] = acc[g][1] = acc[g][2] = acc[g][3] = 0ull;
        #pragma unroll 4
        for (int k4 = 0; k4 < 32; k4++)
            gemv_step<ED>(sW2 + (k4 * 2) * 256 + wofs, s4, eb, 128, k4 * 4, acc);

        // ---- epilogue: SiLU, s-gate, gamma, scatter ----
        float psel = 0.0f;
        #pragma unroll
        for (int g = 0; g < ED; g++) {
            float sgg = __shfl_sync(0xffffffffu, sg, g);
            float4 mg;
            mg.x = silu_f(lohi_sum(acc[g][0]) + sb2v.x) * sgg;
            mg.y = silu_f(lohi_sum(acc[g][1]) + sb2v.y) * sgg;
            mg.z = silu_f(lohi_sum(acc[g][2]) + sb2v.z) * sgg;
            mg.w = silu_f(lohi_sum(acc[g][3]) + sb2v.w) * sgg;

            float p = mg.x * wcv.x + mg.y * wcv.y + mg.z * wcv.z + mg.w * wcv.w;
            #pragma unroll
            for (int o = 16; o; o >>= 1)
                p += __shfl_xor_sync(0xffffffffu, p, o);

            int okg = __shfl_sync(0xffffffffu, okflag, g);
            int dg  = __shfl_sync(0xffffffffu, dd, g);
            if (okg) red_add_v4(g_msum + (size_t)dg * 128 + lane * 4, mg);
            if (lane == g) psel = p;
        }
        if (lane < ED && have) {
            const float gam = psel + bcv;
            atomicAdd(g_coord + dd * 3 + 0, gam * dx);
            atomicAdd(g_coord + dd * 3 + 1, gam * dy);
            atomicAdd(g_coord + dd * 3 + 2, gam * dz);
            atomicAdd(g_deg + dd, 1.0f);
        }
    }
}

// ------------------------------- node ---------------------------------------
// SMEM floats: sWn1[128*256]=32768  sWn2[64*256]=16384  biases 256
//              sE[NW_N*ND*128]=8192  -> 57600 floats = 230,400 B
__global__ __launch_bounds__(TPB_N, 1)
void node_kernel(const float* __restrict__ x, const float* __restrict__ pos,
                 const float* __restrict__ Wn1, const float* __restrict__ bn1,
                 const float* __restrict__ Wn2, const float* __restrict__ bn2,
                 float* __restrict__ xout, float* __restrict__ posout,
                 int N)
{
    extern __shared__ float sm[];
    float* sW1 = sm;                  // 128 k2-rows x 256
    float* sW2 = sW1 + 128 * 256;     // 64 k2-rows x 256
    float* sb1 = sW2 + 64 * 256;
    float* sb2 = sb1 + 128;
    float* sE  = sb2 + 128;

    const int tid = threadIdx.x;
    for (int idx = tid; idx < 256 * 128; idx += TPB_N) {
        int k = idx >> 7, j = idx & 127;
        sW1[wswz(k, j)] = Wn1[idx];
    }
    for (int idx = tid; idx < 128 * 128; idx += TPB_N) {
        int k = idx >> 7, j = idx & 127;
        sW2[wswz(k, j)] = Wn2[idx];
    }
    for (int i = tid; i < 128; i += TPB_N) { sb1[i] = bn1[i]; sb2[i] = bn2[i]; }
    __syncthreads();

    const int lane = tid & 31;
    const int w    = tid >> 5;
    float* eb = sE + w * (ND * 128);

    const int wofs = lane * 8;
    const int s4   = ((lane >> 2) & 1) * 4;
    const float4 sb1v = *(const float4*)(sb1 + lane * 4);
    const float4 sb2v = *(const float4*)(sb2 + lane * 4);

    const int bstride = gridDim.x * NW_N * ND;
    for (int b0 = (blockIdx.x * NW_N + w) * ND; b0 < N; b0 += bstride) {

        int nm = b0 + lane;
        float inv = 1.0f;
        if (lane < ND && nm < N) inv = 1.0f / fmaxf(g_deg[nm], 1.0f);

        unsigned long long acc[ND][4];
        #pragma unroll
        for (int g = 0; g < ND; g++)
            acc[g][0] = acc[g][1] = acc[g][2] = acc[g][3] = 0ull;

        // ---- layer 1 phase A: rows 0..127 with x ----
        __syncwarp();
        #pragma unroll
        for (int g = 0; g < ND; g++) {
            int ng = b0 + g; if (ng >= N) ng = N - 1;
            *(float4*)(eb + g * 128 + lane * 4) =
                *(const float4*)(x + (size_t)ng * 128 + lane * 4);
        }
        __syncwarp();
        #pragma unroll 4
        for (int k4 = 0; k4 < 32; k4++)
            gemv_step<ND>(sW1 + (k4 * 2) * 256 + wofs, s4, eb, 128, k4 * 4, acc);

        // ---- layer 1 phase B: rows 128..255 with m_sum/deg ----
        __syncwarp();
        #pragma unroll
        for (int g = 0; g < ND; g++) {
            int ng = b0 + g; if (ng >= N) ng = N - 1;
            float ig = __shfl_sync(0xffffffffu, inv, g);
            float4 ms = *(const float4*)(g_msum + (size_t)ng * 128 + lane * 4);
            ms.x *= ig; ms.y *= ig; ms.z *= ig; ms.w *= ig;
            *(float4*)(eb + g * 128 + lane * 4) = ms;
        }
        __syncwarp();
        #pragma unroll 4
        for (int k4 = 0; k4 < 32; k4++)
            gemv_step<ND>(sW1 + ((k4 + 32) * 2) * 256 + wofs, s4, eb, 128, k4 * 4, acc);

        // ---- SiLU, stage h, layer 2 ----
        __syncwarp();
        #pragma unroll
        for (int g = 0; g < ND; g++) {
            float4 h;
            h.x = silu_f(lohi_sum(acc[g][0]) + sb1v.x);
            h.y = silu_f(lohi_sum(acc[g][1]) + sb1v.y);
            h.z = silu_f(lohi_sum(acc[g][2]) + sb1v.z);
            h.w = silu_f(lohi_sum(acc[g][3]) + sb1v.w);
            *(float4*)(eb + g * 128 + lane * 4) = h;
            acc[g][0] = acc[g][1] = acc[g][2] = acc[g][3] = 0ull;
        }
        __syncwarp();

        #pragma unroll 4
        for (int k4 = 0; k4 < 32; k4++)
            gemv_step<ND>(sW2 + (k4 * 2) * 256 + wofs, s4, eb, 128, k4 * 4, acc);

        #pragma unroll
        for (int g = 0; g < ND; g++) {
            int ng = b0 + g;
            if (ng < N) {
                float4 o;
                o.x = lohi_sum(acc[g][0]) + sb2v.x;
                o.y = lohi_sum(acc[g][1]) + sb2v.y;
                o.z = lohi_sum(acc[g][2]) + sb2v.z;
                o.w = lohi_sum(acc[g][3]) + sb2v.w;
                *(float4*)(xout + (size_t)ng * 128 + lane * 4) = o;
                float ig = __shfl_sync(0xffffffffu, inv, g);
                if (lane < 3)
                    posout[ng * 3 + lane] =
                        pos[ng * 3 + lane] + g_coord[ng * 3 + lane] * ig;
            }
        }
    }
}

// ------------------------------- launch --------------------------------------
extern "C" void kernel_launch(void* const* d_in, const int* in_sizes, int n_in,
                              void* d_out, int out_size) {
    const float* x     = (const float*)d_in[0];
    const float* pos   = (const float*)d_in[1];
    const void*  ei    = d_in[2];
    const float* eattr = (const float*)d_in[3];
    const float* s     = (const float*)d_in[4];
    const float* We1   = (const float*)d_in[5];
    const float* be1   = (const float*)d_in[6];
    const float* We2   = (const float*)d_in[7];
    const float* be2   = (const float*)d_in[8];
    const float* Wn1   = (const float*)d_in[9];
    const float* bn1   = (const float*)d_in[10];
    const float* Wn2   = (const float*)d_in[11];
    const float* bn2   = (const float*)d_in[12];
    const float* Wc    = (const float*)d_in[13];
    const float* bc    = (const float*)d_in[14];

    const int N = in_sizes[0] / 128;
    const int E = in_sizes[2] / 2;

    float* xout   = (float*)d_out;
    float* posout = (float*)d_out + (size_t)N * 128;

    int dev = 0, nsm = 148;
    cudaGetDevice(&dev);
    cudaDeviceGetAttribute(&nsm, cudaDevAttrMultiProcessorCount, dev);

    const size_t smem_pre  = (size_t)(64 * 256 + 64 * 256 +
                                      NW_P * ND_P * 128) * sizeof(float);  // 163,840
    const size_t smem_edge = (size_t)(64 * 256 + 5 * 128 +
                                      NW_E * ED * 128) * sizeof(float);    // 117,248
    const size_t smem_node = (size_t)(128 * 256 + 64 * 256 + 2 * 128 +
                                      NW_N * ND * 128) * sizeof(float);    // 230,400

    cudaFuncSetAttribute(pre_kernel,  cudaFuncAttributeMaxDynamicSharedMemorySize,
                         (int)smem_pre);
    cudaFuncSetAttribute(edge_kernel, cudaFuncAttributeMaxDynamicSharedMemorySize,
                         (int)smem_edge);
    cudaFuncSetAttribute(node_kernel, cudaFuncAttributeMaxDynamicSharedMemorySize,
                         (int)smem_node);

    zero_kernel<<<256, 256>>>(N);
    detect_kernel<<<16, 256>>>((const unsigned int*)ei, E);
    pre_kernel<<<nsm, TPB_P, smem_pre>>>(x, We1, N);
    edge_kernel<<<nsm, TPB_E, smem_edge>>>(pos,
                                           (const int*)ei, (const long long*)ei,
                                           eattr, s,
                                           We1, be1, We2, be2, Wc, bc, E, N);
    node_kernel<<<nsm, TPB_N, smem_node>>>(x, pos, Wn1, bn1, Wn2, bn2,
                                           xout, posout, N);
}